// round 4
// baseline (speedup 1.0000x reference)
#include <cuda_runtime.h>

// ---------------------------------------------------------------------------
// Micromagnetic LLG solver (RK4, 5-point exchange laplacian, SOT, demag-z).
// Persistent single-kernel design:
//   - one thread per cell (256x256), m kept in registers across all steps
//   - double-buffered global field for neighbor (laplacian) exchange
//   - custom sense-reversal grid barrier between RK4 stages
//   - all field traffic via __ldcg/__stcg (L2-coherent, skips stale L1)
// ---------------------------------------------------------------------------

#define NXg 256
#define NYg 256
#define NCELL (NXg * NYg)
#define TSTEPS 256
#define NSRC 3
#define NPROBE 5
#define NSIG 2
#define RELAX_STEPS 100

#define NB 128   // blocks  (<= 148 SMs -> guaranteed co-resident single wave)
#define NT 512   // threads (NB*NT == NCELL exactly)

// field buffers: [parity][component][cell]
__device__ float g_buf[2][3 * NCELL];
// grid barrier state
__device__ unsigned int g_cnt;
__device__ volatile unsigned int g_gen;

struct V3 { float x, y, z; };

__device__ __forceinline__ V3 vcross(const V3 a, const V3 b) {
    V3 r;
    r.x = a.y * b.z - a.z * b.y;
    r.y = a.z * b.x - a.x * b.z;
    r.z = a.x * b.y - a.y * b.x;
    return r;
}

// Sense-reversal grid barrier. All NB CTAs are co-resident (single wave),
// so spinning is safe. Release: __threadfence before arrive publishes field
// writes; last arriver resets count, fences, bumps generation.
__device__ __forceinline__ void gsync() {
    __syncthreads();
    if (threadIdx.x == 0) {
        __threadfence();
        unsigned int gen = g_gen;
        if (atomicAdd(&g_cnt, 1u) == (unsigned)(NB - 1)) {
            g_cnt = 0u;
            __threadfence();
            g_gen = gen + 1u;
        } else {
            while (g_gen == gen) { }
        }
    }
    __syncthreads();
}

// Torque evaluation for one cell. Center value `cm` is in registers;
// the four neighbors come from the current global stage buffer.
__device__ __forceinline__ V3 torque(const V3 cm, const float* __restrict__ buf,
                                     int iN, int iS, int iW, int iE,
                                     const V3 Bc, float ce, float cd, float sig,
                                     float alpha, float inv) {
    const float* b0 = buf;
    const float* b1 = buf + NCELL;
    const float* b2 = buf + 2 * NCELL;

    float lx = __ldcg(b0 + iN) + __ldcg(b0 + iS) + __ldcg(b0 + iW) + __ldcg(b0 + iE) - 4.0f * cm.x;
    float ly = __ldcg(b1 + iN) + __ldcg(b1 + iS) + __ldcg(b1 + iW) + __ldcg(b1 + iE) - 4.0f * cm.y;
    float lz = __ldcg(b2 + iN) + __ldcg(b2 + iS) + __ldcg(b2 + iW) + __ldcg(b2 + iE) - 4.0f * cm.z;

    V3 B;
    B.x = Bc.x + ce * lx;
    B.y = Bc.y + ce * ly;
    B.z = Bc.z + ce * lz + cd * cm.z + sig;   // demag only on z; source on z

    V3 mxB   = vcross(cm, B);
    V3 mxmxB = vcross(cm, mxB);

    // SOT: C_SOT * m x (m x p), p = (0,1,0);  m x p = (-m.z, 0, m.x)
    V3 mxp;  mxp.x = -cm.z; mxp.y = 0.0f; mxp.z = cm.x;
    V3 sot = vcross(cm, mxp);
    const float C_SOT = 1.0e-4f;

    V3 k;
    k.x = -inv * (mxB.x + alpha * mxmxB.x) + C_SOT * sot.x;
    k.y = -inv * (mxB.y + alpha * mxmxB.y) + C_SOT * sot.y;
    k.z = -inv * (mxB.z + alpha * mxmxB.z) + C_SOT * sot.z;
    return k;
}

// One RK4 step (4 stages, 4 grid syncs). On exit, buf[cur] holds the new m.
__device__ __forceinline__ void rk4_step(V3& m, int& cur, int ic,
                                         int iN, int iS, int iW, int iE,
                                         const V3 Bc, float ce, float cd,
                                         float sig, float alpha, float inv,
                                         float h, float h6) {
    V3 s = m;                 // current stage field value at this cell
    V3 acc = {0.f, 0.f, 0.f};
    const float cst[3] = {0.5f, 0.5f, 1.0f};
    const float wst[4] = {1.0f, 2.0f, 2.0f, 1.0f};

#pragma unroll
    for (int st = 0; st < 4; ++st) {
        V3 k = torque(s, g_buf[cur], iN, iS, iW, iE, Bc, ce, cd, sig, alpha, inv);
        acc.x += wst[st] * k.x;
        acc.y += wst[st] * k.y;
        acc.z += wst[st] * k.z;

        if (st < 3) {
            float c = cst[st] * h;
            s.x = m.x + c * k.x;
            s.y = m.y + c * k.y;
            s.z = m.z + c * k.z;
        } else {
            m.x += h6 * acc.x;
            m.y += h6 * acc.y;
            m.z += h6 * acc.z;
            s = m;
        }
        float* wb = g_buf[cur ^ 1];
        __stcg(wb + ic,            s.x);
        __stcg(wb + NCELL + ic,    s.y);
        __stcg(wb + 2 * NCELL + ic, s.z);
        cur ^= 1;
        gsync();
    }
}

__global__ void __launch_bounds__(NT, 1)
mm_solver_kernel(const float* __restrict__ sigarr,   // [NSIG, TSTEPS, NSRC]
                 const float* __restrict__ Bext,     // [1,3,NX,NY]
                 const float* __restrict__ msat,     // scalar
                 const int*   __restrict__ srcp,     // [NSRC,2]
                 const int*   __restrict__ probep,   // [NPROBE,2]
                 const int*   __restrict__ fb,       // scalar
                 float*       __restrict__ out)      // [NSIG, TSTEPS, NPROBE]
{
    const int id = blockIdx.x * NT + threadIdx.x;    // 0..65535
    const int x = id >> 8;
    const int y = id & (NYg - 1);
    const int ic = id;
    const int iN = (x > 0)       ? id - NYg : id;    // edge-clamped (pad mode='edge')
    const int iS = (x < NXg - 1) ? id + NYg : id;
    const int iW = (y > 0)       ? id - 1   : id;
    const int iE = (y < NYg - 1) ? id + 1   : id;

    const float Msat = msat[0];
    const int finalb = fb[0];

    V3 Bc;
    Bc.x = Bext[ic];
    Bc.y = Bext[NCELL + ic];
    Bc.z = Bext[2 * NCELL + ic];

    // constants (double intermediate to match scalar precision)
    const float ce = (float)(2.0 * 3.5e-12 / ((double)Msat * (5e-8 * 5e-8)));       // 2A/(Ms dx^2)
    const float cd = (float)(-(1.2566370614359172e-06) * (double)Msat);             // -mu0*Ms
    const float h  = (float)(175950000000.0 * 5e-12);                               // gamma*dt
    const float h6 = (float)((175950000000.0 * 5e-12) / 6.0);

    int srcj = -1;
#pragma unroll
    for (int j = 0; j < NSRC; ++j)
        if (srcp[2 * j] == x && srcp[2 * j + 1] == y) srcj = j;
    int prj = -1;
#pragma unroll
    for (int j = 0; j < NPROBE; ++j)
        if (probep[2 * j] == x && probep[2 * j + 1] == y) prj = j;

    // ---- init: m0 = (0,1,0) everywhere ----
    V3 m = {0.0f, 1.0f, 0.0f};
    {
        float* wb = g_buf[0];
        __stcg(wb + ic,             m.x);
        __stcg(wb + NCELL + ic,     m.y);
        __stcg(wb + 2 * NCELL + ic, m.z);
    }
    int cur = 0;
    gsync();

    // ---- relaxation phase: alpha = 0.5, no source ----
    {
        const float alpha = 0.5f;
        const float inv = 1.0f / (1.0f + alpha * alpha);
        for (int i = 0; i < RELAX_STEPS; ++i)
            rk4_step(m, cur, ic, iN, iS, iW, iE, Bc, ce, cd, 0.0f, alpha, inv, h, h6);
    }
    const V3 mrel = m;

    // ---- run phase: alpha = 0.01, sources driven by signal ----
    const float alpha = 0.01f;
    const float inv = 1.0f / (1.0f + alpha * alpha);

    for (int si = 0; si < NSIG; ++si) {
        if (si > 0) {
            // restart from relaxed state
            m = mrel;
            float* wb = g_buf[cur];
            __stcg(wb + ic,             m.x);
            __stcg(wb + NCELL + ic,     m.y);
            __stcg(wb + 2 * NCELL + ic, m.z);
            gsync();
        }
        for (int t = 0; t < TSTEPS; ++t) {
            float sig = 0.0f;
            if (srcj >= 0)
                sig = __ldg(sigarr + ((si * TSTEPS + t) * NSRC + srcj));

            rk4_step(m, cur, ic, iN, iS, iW, iE, Bc, ce, cd, sig, alpha, inv, h, h6);

            if (prj >= 0) {
                float v = finalb ? (m.z - mrel.z) * Msat : m.z;
                out[(si * TSTEPS + t) * NPROBE + prj] = v;
            }
        }
    }
}

extern "C" void kernel_launch(void* const* d_in, const int* in_sizes, int n_in,
                              void* d_out, int out_size) {
    const float* list_signal = (const float*)d_in[0];
    const float* B_ext       = (const float*)d_in[1];
    const float* Msat        = (const float*)d_in[2];
    const int*   src_pos     = (const int*)d_in[3];
    const int*   probe_pos   = (const int*)d_in[4];
    const int*   final_board = (const int*)d_in[5];
    float*       out         = (float*)d_out;

    mm_solver_kernel<<<NB, NT>>>(list_signal, B_ext, Msat, src_pos, probe_pos,
                                 final_board, out);
}